// round 15
// baseline (speedup 1.0000x reference)
#include <cuda_runtime.h>
#include <cuda_bf16.h>
#include <cstdint>

// ---------------- problem constants ----------------
constexpr int Tn   = 128;   // seq len
constexpr int Bq   = 256;   // batch
constexpr int Hh   = 512;   // hidden
constexpr int Ee   = 16;    // embed
constexpr int Ln   = 4;     // layers
constexpr int G4   = 2048;  // 4H

// tf32 K-permutation within each 16-block: k' = (k&3)*4 + (k>>2)
__host__ __device__ __forceinline__ int perm16(int k) {
    return (k & ~15) | (((k & 3) << 2) | ((k >> 2) & 3));
}
// bf16 (m16n8k16) K-permutation within each 16-block:
// store order {0,1,8,9, 2,3,10,11, 4,5,12,13, 6,7,14,15} -> thread tg's chunk = {2tg,2tg+1,2tg+8,2tg+9}
__host__ __device__ __forceinline__ int perm16b(int k) {
    int kk = k & 15;
    return (k & ~15) + 4 * ((kk & 7) >> 1) + 2 * (kk >> 3) + (kk & 1);
}

// ---------------- device scratch (static; no allocation) ----------------
__device__ float d_Wih0[2 * G4 * Ee];                  // tf32, perm16 K
__device__ float d_Whh0[2 * G4 * Hh];                  // tf32, perm16 K
__device__ __nv_bfloat16 d_WihB[3 * 2 * G4 * 1024];    // bf16, perm16b K  (l>=1 x-path)
__device__ float d_WhhL[3 * 2 * G4 * Hh];              // tf32, perm16 K
__device__ float d_bias[Ln * 2 * G4];
__device__ float d_x0[Tn * Bq * Ee];                   // tf32, perm16 features
__device__ float d_h[3][Ln * 2 * Bq * Hh];             // tf32 h ring, perm16 features
__device__ __nv_bfloat16 d_hb[3][Ln * 2 * Bq * Hh];    // bf16 h ring, perm16b features
__device__ float d_c[Ln * 2 * Bq * Hh];

// ---------------- helpers ----------------
__device__ __forceinline__ float tf32r(float x) {
    uint32_t u;
    asm("cvt.rna.tf32.f32 %0, %1;" : "=r"(u) : "f"(x));
    return __uint_as_float(u);
}
__device__ __forceinline__ void cp16(void* dst, const void* src) {
    unsigned s = (unsigned)__cvta_generic_to_shared(dst);
    asm volatile("cp.async.cg.shared.global [%0], [%1], 16;\n" :: "r"(s), "l"(src));
}
__device__ __forceinline__ void cp8(void* dst, const void* src) {
    unsigned s = (unsigned)__cvta_generic_to_shared(dst);
    asm volatile("cp.async.ca.shared.global [%0], [%1], 8;\n" :: "r"(s), "l"(src));
}
__device__ __forceinline__ void cp_commit() { asm volatile("cp.async.commit_group;\n"); }
template <int N>
__device__ __forceinline__ void cp_wait() { asm volatile("cp.async.wait_group %0;\n" :: "n"(N)); }

__device__ __forceinline__ void mma_tf32(float* c,
                                         uint32_t a0, uint32_t a1, uint32_t a2, uint32_t a3,
                                         uint32_t b0, uint32_t b1) {
    asm volatile(
        "mma.sync.aligned.m16n8k8.row.col.f32.tf32.tf32.f32 "
        "{%0,%1,%2,%3},{%4,%5,%6,%7},{%8,%9},{%0,%1,%2,%3};\n"
        : "+f"(c[0]), "+f"(c[1]), "+f"(c[2]), "+f"(c[3])
        : "r"(a0), "r"(a1), "r"(a2), "r"(a3), "r"(b0), "r"(b1));
}
__device__ __forceinline__ void mma_bf16(float* c,
                                         uint32_t a0, uint32_t a1, uint32_t a2, uint32_t a3,
                                         uint32_t b0, uint32_t b1) {
    asm volatile(
        "mma.sync.aligned.m16n8k16.row.col.f32.bf16.bf16.f32 "
        "{%0,%1,%2,%3},{%4,%5,%6,%7},{%8,%9},{%0,%1,%2,%3};\n"
        : "+f"(c[0]), "+f"(c[1]), "+f"(c[2]), "+f"(c[3])
        : "r"(a0), "r"(a1), "r"(a2), "r"(a3), "r"(b0), "r"(b1));
}
__device__ __forceinline__ float sigf(float x) { return 1.0f / (1.0f + __expf(-x)); }

// ---------------- init ----------------
__global__ void init_kernel(const int* __restrict__ tokens, const float* __restrict__ embed,
                            const float* __restrict__ Wih0, const float* __restrict__ Whh0,
                            const float* __restrict__ bih0, const float* __restrict__ bhh0,
                            const float* __restrict__ Wih,  const float* __restrict__ Whh,
                            const float* __restrict__ bih,  const float* __restrict__ bhh) {
    const int idx0   = blockIdx.x * blockDim.x + threadIdx.x;
    const int stride = gridDim.x * blockDim.x;

    for (int i = idx0; i < 2 * G4 * Ee; i += stride) {
        int row = i / Ee, k = i % Ee;
        d_Wih0[row * Ee + perm16(k)] = tf32r(Wih0[i]);
    }
    for (int i = idx0; i < 2 * G4 * Hh; i += stride) {
        int row = i / Hh, k = i % Hh;
        d_Whh0[row * Hh + perm16(k)] = tf32r(Whh0[i]);
    }
    for (int i = idx0; i < 3 * 2 * G4 * 1024; i += stride) {
        int row = i / 1024, k = i % 1024;
        d_WihB[row * 1024 + perm16b(k)] = __float2bfloat16(Wih[i]);
    }
    for (int i = idx0; i < 3 * 2 * G4 * Hh; i += stride) {
        int row = i / Hh, k = i % Hh;
        d_WhhL[row * Hh + perm16(k)] = tf32r(Whh[i]);
    }
    for (int i = idx0; i < Ln * 2 * G4; i += stride) {
        int l = i / (2 * G4), r = i % (2 * G4);
        d_bias[i] = (l == 0) ? (bih0[r] + bhh0[r])
                             : (bih[(l - 1) * 2 * G4 + r] + bhh[(l - 1) * 2 * G4 + r]);
    }
    for (int i = idx0; i < Tn * Bq * Ee; i += stride) {
        int t = i / (Bq * Ee);
        int rem = i % (Bq * Ee);
        int b = rem / Ee, e = rem % Ee;
        d_x0[t * Bq * Ee + b * Ee + perm16(e)] = tf32r(embed[tokens[t * Bq + b] * Ee + e]);
    }
    for (int i = idx0; i < Ln * 2 * Bq * Hh; i += stride) {
        d_h[0][i] = 0.f; d_h[1][i] = 0.f; d_h[2][i] = 0.f;
        __nv_bfloat16 z = __float2bfloat16(0.f);
        d_hb[0][i] = z; d_hb[1][i] = z; d_hb[2][i] = z;
        d_c[i] = 0.f;
    }
}

// ---------------- shared epilogue: gates in gt[64][80] -> LSTM cell update ----------------
__device__ __forceinline__ void cell_epilogue(float* gt, int tid, int b0, int j0,
                                              const float* biasD, float* cstD,
                                              float* houtD, __nv_bfloat16* houtB) {
    const int jj = tid & 15, rbase = tid >> 4;
    const int j = j0 + jj;
    const float bi = biasD[0 * Hh + j];
    const float bf = biasD[1 * Hh + j];
    const float bg = biasD[2 * Hh + j];
    const float bo = biasD[3 * Hh + j];
    const int jp  = j0 + (((jj & 3) << 2) | (jj >> 2));                          // perm16
    const int jpb = j0 + 4 * ((jj & 7) >> 1) + 2 * (jj >> 3) + (jj & 1);         // perm16b
    #pragma unroll
    for (int q = 0; q < 8; ++q) {
        int row = rbase + q * 8;
        int b = b0 + row;
        float gi = gt[row * 80 +  0 + jj] + bi;
        float gf = gt[row * 80 + 16 + jj] + bf;
        float gg = gt[row * 80 + 32 + jj] + bg;
        float go = gt[row * 80 + 48 + jj] + bo;
        float i_ = sigf(gi), f_ = sigf(gf), g_ = tanhf(gg), o_ = sigf(go);
        float cn = fmaf(f_, cstD[b * Hh + j], i_ * g_);
        cstD[b * Hh + j] = cn;
        float hv = o_ * tanhf(cn);
        houtD[b * Hh + jp]  = tf32r(hv);
        houtB[b * Hh + jpb] = __float2bfloat16(hv);
    }
}

// ---------------- layer 0 cell (KIN = Ee = 16, pure tf32) ----------------
__device__ __forceinline__ void lstm_cell0(int t, int dir, float* smem) {
    constexpr int NIT = (Ee + Hh) / 16;   // 33
    const int tid = threadIdx.x;
    const int mt = blockIdx.x, jt = blockIdx.y;
    const int b0 = mt * 64, j0 = jt * 16;
    const int rb = (t + 2) % 3, wb = t % 3;

    const float* __restrict__ hprevD = d_h[rb] + dir * Bq * Hh;
    float* __restrict__ houtD = d_h[wb] + dir * Bq * Hh;
    __nv_bfloat16* __restrict__ houtB = d_hb[wb] + dir * Bq * Hh;
    float* __restrict__ cstD = d_c + dir * Bq * Hh;
    const float* __restrict__ xbase = d_x0 + t * Bq * Ee;
    const float* __restrict__ WihD = d_Wih0 + dir * G4 * Ee;
    const float* __restrict__ WhhD = d_Whh0 + dir * G4 * Hh;

    const int lrow = tid >> 2, lgrp = tid & 3;
    uint32_t aSm[2], bSm[2];
    int aRow[2], bIh[2], bHh[2];
    #pragma unroll
    for (int q = 0; q < 2; ++q) {
        int row = lrow + q * 32;
        uint32_t sw = ((lgrp ^ (row & 3)) << 2);
        aSm[q] = row * 16 + sw;
        bSm[q] = 1024 + row * 16 + sw;
        aRow[q] = b0 + row;
        int wrow = (row >> 4) * Hh + j0 + (row & 15);
        bIh[q] = wrow * Ee + lgrp * 4;
        bHh[q] = wrow * Hh + lgrp * 4;
    }
    auto load_stage = [&](int it, int buf) {
        const int k0 = it * 16;
        const int kk = k0 + lgrp * 4;
        float* st = smem + buf * 2048;
        if (kk < Ee) {
            #pragma unroll
            for (int q = 0; q < 2; ++q) cp16(&st[aSm[q]], xbase + aRow[q] * Ee + kk);
            #pragma unroll
            for (int q = 0; q < 2; ++q) cp16(&st[bSm[q]], WihD + bIh[q] + k0);
        } else {
            #pragma unroll
            for (int q = 0; q < 2; ++q) cp16(&st[aSm[q]], hprevD + aRow[q] * Hh + (kk - Ee));
            #pragma unroll
            for (int q = 0; q < 2; ++q) cp16(&st[bSm[q]], WhhD + bHh[q] + (k0 - Ee));
        }
        cp_commit();
    };

    const int lane = tid & 31, wid = tid >> 5;
    const int wm = wid & 1, wn = wid >> 1;
    const int g = lane >> 2, tg = lane & 3;
    const uint32_t asw = ((tg ^ (g & 3)) << 2);
    uint32_t aOff[2][2], bOff[4];
    #pragma unroll
    for (int mi = 0; mi < 2; ++mi) {
        int r = wm * 32 + mi * 16 + g;
        aOff[mi][0] = r * 16 + asw;
        aOff[mi][1] = (r + 8) * 16 + asw;
    }
    #pragma unroll
    for (int ni = 0; ni < 4; ++ni) {
        int n = wn * 32 + ni * 8 + g;
        bOff[ni] = 1024 + n * 16 + ((tg ^ (n & 3)) << 2);
    }

    float acc[2][4][4];
    #pragma unroll
    for (int i = 0; i < 2; i++)
        #pragma unroll
        for (int jx = 0; jx < 4; jx++)
            #pragma unroll
            for (int k = 0; k < 4; k++) acc[i][jx][k] = 0.f;

    load_stage(0, 0);
    load_stage(1, 1);
    int rdOff = 0, ldBuf = 2;
    for (int it = 0; it < NIT; ++it) {
        if (it + 1 < NIT) cp_wait<1>(); else cp_wait<0>();
        __syncthreads();
        if (it + 2 < NIT) { load_stage(it + 2, ldBuf); if (++ldBuf == 3) ldBuf = 0; }
        const float* A = smem + rdOff;
        if ((rdOff += 2048) == 6144) rdOff = 0;
        float4 bv[4];
        #pragma unroll
        for (int ni = 0; ni < 4; ++ni)
            bv[ni] = *reinterpret_cast<const float4*>(A + bOff[ni]);
        #pragma unroll
        for (int mi = 0; mi < 2; ++mi) {
            float4 a0 = *reinterpret_cast<const float4*>(A + aOff[mi][0]);
            float4 a1 = *reinterpret_cast<const float4*>(A + aOff[mi][1]);
            #pragma unroll
            for (int ni = 0; ni < 4; ++ni) {
                mma_tf32(acc[mi][ni],
                         __float_as_uint(a0.x), __float_as_uint(a1.x),
                         __float_as_uint(a0.y), __float_as_uint(a1.y),
                         __float_as_uint(bv[ni].x), __float_as_uint(bv[ni].y));
                mma_tf32(acc[mi][ni],
                         __float_as_uint(a0.z), __float_as_uint(a1.z),
                         __float_as_uint(a0.w), __float_as_uint(a1.w),
                         __float_as_uint(bv[ni].z), __float_as_uint(bv[ni].w));
            }
        }
    }
    __syncthreads();
    float* gt = smem;
    #pragma unroll
    for (int mi = 0; mi < 2; ++mi)
        #pragma unroll
        for (int ni = 0; ni < 4; ++ni) {
            int r = wm * 32 + mi * 16 + g;
            int cc = wn * 32 + ni * 8 + 2 * tg;
            gt[r * 80 + cc]           = acc[mi][ni][0];
            gt[r * 80 + cc + 1]       = acc[mi][ni][1];
            gt[(r + 8) * 80 + cc]     = acc[mi][ni][2];
            gt[(r + 8) * 80 + cc + 1] = acc[mi][ni][3];
        }
    __syncthreads();
    cell_epilogue(gt, tid, b0, j0, d_bias + dir * G4, cstD, houtD, houtB);
}

// ---------------- layer >=1 cell: hybrid bf16 (x-path) + tf32 (h-path) ----------------
// Phase X: 64 iters, m16n8k16 bf16: x[64x1024] * WihB^T.   Stage: A16 64x(16bf16,40B stride) + B16 same.
// Phase H: 32 iters, m16n8k8 tf32:  hprev[64x512] * Whh^T.  Stage: A 64x16 f32 + B 64x16 f32.
// 3 stages x 8KB = 24KB smem; one __syncthreads per iter (same discipline as R12).
__device__ __forceinline__ void lstm_cellX(int t, int l, int dir, float* smem) {
    constexpr int NITX = 64, NIT = 96;
    const int tid = threadIdx.x;
    const int mt = blockIdx.x, jt = blockIdx.y;
    const int b0 = mt * 64, j0 = jt * 16;
    const int rb = (t + 2) % 3, wb = t % 3;

    const float* __restrict__ hprevD = d_h[rb] + (l * 2 + dir) * Bq * Hh;
    float* __restrict__ houtD = d_h[wb] + (l * 2 + dir) * Bq * Hh;
    __nv_bfloat16* __restrict__ houtB = d_hb[wb] + (l * 2 + dir) * Bq * Hh;
    float* __restrict__ cstD = d_c + (l * 2 + dir) * Bq * Hh;
    const __nv_bfloat16* __restrict__ x16_0 = d_hb[wb] + ((l - 1) * 2 + 0) * Bq * Hh;
    const __nv_bfloat16* __restrict__ x16_1 = d_hb[wb] + ((l - 1) * 2 + 1) * Bq * Hh;
    const __nv_bfloat16* __restrict__ WihB = d_WihB + ((l - 1) * 2 + dir) * G4 * 1024;
    const float* __restrict__ WhhD = d_WhhL + ((l - 1) * 2 + dir) * G4 * Hh;

    // ---- load geometry ----
    const int lrow = tid >> 2, lgrp = tid & 3;
    // phase X: slot = tid + q*128: row = slot>>2, t4 = slot&3; 8B chunks, 40B row stride
    uint32_t xaS[2], xbS[2];
    int xaG[2], xbG[2];
    // phase H (f32): same as R12
    uint32_t aSm[2], bSm[2];
    int aRow[2], bHh[2];
    #pragma unroll
    for (int q = 0; q < 2; ++q) {
        int slot = tid + q * 128, row = slot >> 2, t4 = slot & 3;
        uint32_t xsw = (uint32_t)((t4 ^ (row & 3)) << 3);
        xaS[q] = row * 40 + xsw;
        xbS[q] = 2560 + row * 40 + xsw;
        xaG[q] = (b0 + row) * Hh + t4 * 4;
        int wrowx = (row >> 4) * Hh + j0 + (row & 15);
        xbG[q] = wrowx * 1024 + t4 * 4;
        // phase H
        int rowh = lrow + q * 32;
        uint32_t sw = ((lgrp ^ (rowh & 3)) << 2);
        aSm[q] = rowh * 16 + sw;
        bSm[q] = 1024 + rowh * 16 + sw;
        aRow[q] = b0 + rowh;
        int wrow = (rowh >> 4) * Hh + j0 + (rowh & 15);
        bHh[q] = wrow * Hh + lgrp * 4;
    }

    auto load_stage = [&](int it, int buf) {
        char* stc = (char*)(smem + buf * 2048);
        if (it < NITX) {
            const int kk16 = it * 16;
            const __nv_bfloat16* xb = (kk16 & 512) ? x16_1 : x16_0;
            const int ks = kk16 & 511;
            #pragma unroll
            for (int q = 0; q < 2; ++q) cp8(stc + xaS[q], xb + xaG[q] + ks);
            #pragma unroll
            for (int q = 0; q < 2; ++q) cp8(stc + xbS[q], WihB + xbG[q] + kk16);
        } else {
            const int k0 = (it - NITX) * 16;
            const int ko = k0 + lgrp * 4;
            float* st = (float*)stc;
            #pragma unroll
            for (int q = 0; q < 2; ++q) cp16(&st[aSm[q]], hprevD + aRow[q] * Hh + ko);
            #pragma unroll
            for (int q = 0; q < 2; ++q) cp16(&st[bSm[q]], WhhD + bHh[q] + k0);
        }
        cp_commit();
    };

    const int lane = tid & 31, wid = tid >> 5;
    const int wm = wid & 1, wn = wid >> 1;
    const int g = lane >> 2, tg = lane & 3;

    // fragment offsets
    const uint32_t asw = ((tg ^ (g & 3)) << 2);           // tf32 (floats)
    const uint32_t xsw = (uint32_t)((tg ^ (g & 3)) << 3); // bf16 (bytes)
    uint32_t aOff[2][2], bOff[4];     // tf32, float units
    uint32_t xaOff[2][2], xbOff[4];   // bf16, byte units
    #pragma unroll
    for (int mi = 0; mi < 2; ++mi) {
        int r = wm * 32 + mi * 16 + g;
        aOff[mi][0] = r * 16 + asw;
        aOff[mi][1] = (r + 8) * 16 + asw;
        xaOff[mi][0] = r * 40 + xsw;
        xaOff[mi][1] = (r + 8) * 40 + xsw;
    }
    #pragma unroll
    for (int ni = 0; ni < 4; ++ni) {
        int n = wn * 32 + ni * 8 + g;
        bOff[ni] = 1024 + n * 16 + ((tg ^ (n & 3)) << 2);
        xbOff[ni] = 2560 + n * 40 + (uint32_t)((tg ^ (n & 3)) << 3);
    }

    float acc[2][4][4];
    #pragma unroll
    for (int i = 0; i < 2; i++)
        #pragma unroll
        for (int jx = 0; jx < 4; jx++)
            #pragma unroll
            for (int k = 0; k < 4; k++) acc[i][jx][k] = 0.f;

    load_stage(0, 0);
    load_stage(1, 1);
    int rdOff = 0, ldBuf = 2;
    for (int it = 0; it < NIT; ++it) {
        if (it + 1 < NIT) cp_wait<1>(); else cp_wait<0>();
        __syncthreads();
        if (it + 2 < NIT) { load_stage(it + 2, ldBuf); if (++ldBuf == 3) ldBuf = 0; }
        const char* stc = (const char*)(smem + rdOff);
        if ((rdOff += 2048) == 6144) rdOff = 0;

        if (it < NITX) {
            // bf16 phase: 8 LDS.64 + 8 k16-MMAs per warp
            uint2 bv[4];
            #pragma unroll
            for (int ni = 0; ni < 4; ++ni)
                bv[ni] = *reinterpret_cast<const uint2*>(stc + xbOff[ni]);
            #pragma unroll
            for (int mi = 0; mi < 2; ++mi) {
                uint2 alo = *reinterpret_cast<const uint2*>(stc + xaOff[mi][0]);  // (a0, a2)
                uint2 ahi = *reinterpret_cast<const uint2*>(stc + xaOff[mi][1]);  // (a1, a3)
                #pragma unroll
                for (int ni = 0; ni < 4; ++ni)
                    mma_bf16(acc[mi][ni], alo.x, ahi.x, alo.y, ahi.y, bv[ni].x, bv[ni].y);
            }
        } else {
            const float* A = (const float*)stc;
            float4 bv[4];
            #pragma unroll
            for (int ni = 0; ni < 4; ++ni)
                bv[ni] = *reinterpret_cast<const float4*>(A + bOff[ni]);
            #pragma unroll
            for (int mi = 0; mi < 2; ++mi) {
                float4 a0 = *reinterpret_cast<const float4*>(A + aOff[mi][0]);
                float4 a1 = *reinterpret_cast<const float4*>(A + aOff[mi][1]);
                #pragma unroll
                for (int ni = 0; ni < 4; ++ni) {
                    mma_tf32(acc[mi][ni],
                             __float_as_uint(a0.x), __float_as_uint(a1.x),
                             __float_as_uint(a0.y), __float_as_uint(a1.y),
                             __float_as_uint(bv[ni].x), __float_as_uint(bv[ni].y));
                    mma_tf32(acc[mi][ni],
                             __float_as_uint(a0.z), __float_as_uint(a1.z),
                             __float_as_uint(a0.w), __float_as_uint(a1.w),
                             __float_as_uint(bv[ni].z), __float_as_uint(bv[ni].w));
                }
            }
        }
    }
    __syncthreads();
    float* gt = smem;
    #pragma unroll
    for (int mi = 0; mi < 2; ++mi)
        #pragma unroll
        for (int ni = 0; ni < 4; ++ni) {
            int r = wm * 32 + mi * 16 + g;
            int cc = wn * 32 + ni * 8 + 2 * tg;
            gt[r * 80 + cc]           = acc[mi][ni][0];
            gt[r * 80 + cc + 1]       = acc[mi][ni][1];
            gt[(r + 8) * 80 + cc]     = acc[mi][ni][2];
            gt[(r + 8) * 80 + cc + 1] = acc[mi][ni][3];
        }
    __syncthreads();
    cell_epilogue(gt, tid, b0, j0, d_bias + (l * 2 + dir) * G4, cstD, houtD, houtB);
}

// ---------------- wavefront kernel ----------------
// grid = (4 mtiles, 32 jtiles, ncells*2)
__global__ __launch_bounds__(128, 7) void lstm_wave(int w, int lmin) {
    __shared__ __align__(16) float smem[6144];   // 3 stages x 8KB
    const int cell = blockIdx.z >> 1;
    const int dir  = blockIdx.z & 1;
    const int l    = lmin + cell;
    const int t    = w - l;
    if (t < 0 || t >= Tn) return;
    if (l == 0) lstm_cell0(t, dir, smem);
    else        lstm_cellX(t, l, dir, smem);
}

// ---------------- final FC + softmax ----------------
__global__ __launch_bounds__(256) void fc_softmax(const float* __restrict__ fcw,
                                                  const float* __restrict__ fcb,
                                                  float* __restrict__ out) {
    const int b = blockIdx.x;
    const int tid = threadIdx.x, lane = tid & 31, w = tid >> 5;
    __shared__ float sv[64];
    const float* __restrict__ hf = d_h[(Tn - 1) % 3];   // t=127 wrote ring slot 1
    float acc[8] = {0, 0, 0, 0, 0, 0, 0, 0};
    for (int k = lane; k < 8192; k += 32) {
        int s = k >> 10, r = k & 1023, j = r & 511;
        float hv = (r & 512) ? d_c[(s * Bq + b) * Hh + j]
                             : hf[(s * Bq + b) * Hh + perm16(j)];   // h stored permuted
        #pragma unroll
        for (int q = 0; q < 8; ++q)
            acc[q] = fmaf(hv, fcw[(w * 8 + q) * 8192 + k], acc[q]);
    }
    #pragma unroll
    for (int q = 0; q < 8; ++q) {
        float v = acc[q];
        #pragma unroll
        for (int off = 16; off; off >>= 1) v += __shfl_xor_sync(0xffffffffu, v, off);
        if (lane == 0) sv[w * 8 + q] = v + fcb[w * 8 + q];
    }
    __syncthreads();
    if (tid < 32) {
        float v0 = sv[tid], v1 = sv[tid + 32];
        float m = fmaxf(v0, v1);
        #pragma unroll
        for (int off = 16; off; off >>= 1) m = fmaxf(m, __shfl_xor_sync(0xffffffffu, m, off));
        float e0 = expf(v0 - m), e1 = expf(v1 - m);
        float s = e0 + e1;
        #pragma unroll
        for (int off = 16; off; off >>= 1) s += __shfl_xor_sync(0xffffffffu, s, off);
        float inv = 1.0f / s;
        out[b * 64 + tid]      = e0 * inv;
        out[b * 64 + 32 + tid] = e1 * inv;
    }
}

// ---------------- launch ----------------
extern "C" void kernel_launch(void* const* d_in, const int* in_sizes, int n_in,
                              void* d_out, int out_size) {
    const int*   tokens = (const int*)  d_in[0];
    const float* embed  = (const float*)d_in[1];
    const float* Wih0   = (const float*)d_in[2];
    const float* Whh0   = (const float*)d_in[3];
    const float* bih0   = (const float*)d_in[4];
    const float* bhh0   = (const float*)d_in[5];
    const float* Wih    = (const float*)d_in[6];
    const float* Whh    = (const float*)d_in[7];
    const float* bih    = (const float*)d_in[8];
    const float* bhh    = (const float*)d_in[9];
    const float* fcw    = (const float*)d_in[10];
    const float* fcb    = (const float*)d_in[11];
    float*       out    = (float*)d_out;

    init_kernel<<<512, 256>>>(tokens, embed, Wih0, Whh0, bih0, bhh0, Wih, Whh, bih, bhh);

    // wavefront schedule: cells (t, l) with t + l == w are independent
    for (int w = 0; w <= (Tn - 1) + (Ln - 1); ++w) {
        int lmin = max(0, w - (Tn - 1));
        int lmax = min(Ln - 1, w);
        int ncells = lmax - lmin + 1;
        dim3 grid(4, 32, ncells * 2);
        lstm_wave<<<grid, 128>>>(w, lmin);
    }
    fc_softmax<<<Bq, 256>>>(fcw, fcb, out);
}

// round 17
// speedup vs baseline: 1.1183x; 1.1183x over previous
#include <cuda_runtime.h>
#include <cstdint>

// ---------------- problem constants ----------------
constexpr int Tn   = 128;   // seq len
constexpr int Bq   = 256;   // batch
constexpr int Hh   = 512;   // hidden
constexpr int Ee   = 16;    // embed
constexpr int Ln   = 4;     // layers
constexpr int G4   = 2048;  // 4H

// K-permutation within each 16-block: k' = (k&3)*4 + (k>>2)
__host__ __device__ __forceinline__ int perm16(int k) {
    return (k & ~15) | (((k & 3) << 2) | ((k >> 2) & 3));
}

// ---------------- device scratch (static; no allocation) ----------------
// All K-dimensions stored PERMUTED by perm16. h is stored feature-permuted.
__device__ float d_Wih0[2 * G4 * Ee];
__device__ float d_Whh0[2 * G4 * Hh];
__device__ float d_WihL[3 * 2 * G4 * 1024];
__device__ float d_WhhL[3 * 2 * G4 * Hh];
__device__ float d_bias[Ln * 2 * G4];           // bih + bhh (unit-indexed, NOT permuted)
__device__ float d_x0[Tn * Bq * Ee];            // rounded embed[tokens], feature-permuted
__device__ float d_h[3][Ln * 2 * Bq * Hh];      // 3-deep ring, feature-permuted
__device__ float d_c[Ln * 2 * Bq * Hh];         // c state (unit-indexed, plain)

// ---------------- helpers ----------------
__device__ __forceinline__ float tf32r(float x) {
    uint32_t u;
    asm("cvt.rna.tf32.f32 %0, %1;" : "=r"(u) : "f"(x));
    return __uint_as_float(u);
}

__device__ __forceinline__ void cp16(float* dst, const float* src) {
    unsigned s = (unsigned)__cvta_generic_to_shared(dst);
    asm volatile("cp.async.cg.shared.global [%0], [%1], 16;\n" :: "r"(s), "l"(src));
}
__device__ __forceinline__ void cp_commit() { asm volatile("cp.async.commit_group;\n"); }
template <int N>
__device__ __forceinline__ void cp_wait() { asm volatile("cp.async.wait_group %0;\n" :: "n"(N)); }

__device__ __forceinline__ void mma_tf32(float* c,
                                         uint32_t a0, uint32_t a1, uint32_t a2, uint32_t a3,
                                         uint32_t b0, uint32_t b1) {
    asm volatile(
        "mma.sync.aligned.m16n8k8.row.col.f32.tf32.tf32.f32 "
        "{%0,%1,%2,%3},{%4,%5,%6,%7},{%8,%9},{%0,%1,%2,%3};\n"
        : "+f"(c[0]), "+f"(c[1]), "+f"(c[2]), "+f"(c[3])
        : "r"(a0), "r"(a1), "r"(a2), "r"(a3), "r"(b0), "r"(b1));
}

__device__ __forceinline__ float sigf(float x) { return 1.0f / (1.0f + __expf(-x)); }
// fast tanh: MUFU-based, overflow-safe (e = exp(-2|x|) in (0,1]), sign restored
__device__ __forceinline__ float tanhf_fast(float x) {
    float e = __expf(-2.0f * fabsf(x));
    float r = (1.0f - e) * __frcp_rn(1.0f + e);
    return copysignf(r, x);
}

// ---------------- init: tf32-round + K-permute weights, gather+permute x0, zero state ----------------
__global__ void init_kernel(const int* __restrict__ tokens, const float* __restrict__ embed,
                            const float* __restrict__ Wih0, const float* __restrict__ Whh0,
                            const float* __restrict__ bih0, const float* __restrict__ bhh0,
                            const float* __restrict__ Wih,  const float* __restrict__ Whh,
                            const float* __restrict__ bih,  const float* __restrict__ bhh) {
    const int idx0   = blockIdx.x * blockDim.x + threadIdx.x;
    const int stride = gridDim.x * blockDim.x;

    for (int i = idx0; i < 2 * G4 * Ee; i += stride) {
        int row = i / Ee, k = i % Ee;
        d_Wih0[row * Ee + perm16(k)] = tf32r(Wih0[i]);
    }
    for (int i = idx0; i < 2 * G4 * Hh; i += stride) {
        int row = i / Hh, k = i % Hh;
        d_Whh0[row * Hh + perm16(k)] = tf32r(Whh0[i]);
    }
    for (int i = idx0; i < 3 * 2 * G4 * 1024; i += stride) {
        int row = i / 1024, k = i % 1024;
        d_WihL[row * 1024 + perm16(k)] = tf32r(Wih[i]);
    }
    for (int i = idx0; i < 3 * 2 * G4 * Hh; i += stride) {
        int row = i / Hh, k = i % Hh;
        d_WhhL[row * Hh + perm16(k)] = tf32r(Whh[i]);
    }
    for (int i = idx0; i < Ln * 2 * G4; i += stride) {
        int l = i / (2 * G4), r = i % (2 * G4);
        d_bias[i] = (l == 0) ? (bih0[r] + bhh0[r])
                             : (bih[(l - 1) * 2 * G4 + r] + bhh[(l - 1) * 2 * G4 + r]);
    }
    for (int i = idx0; i < Tn * Bq * Ee; i += stride) {
        int t = i / (Bq * Ee);
        int rem = i % (Bq * Ee);
        int b = rem / Ee, e = rem % Ee;
        d_x0[t * Bq * Ee + b * Ee + perm16(e)] = tf32r(embed[tokens[t * Bq + b] * Ee + e]);
    }
    for (int i = idx0; i < Ln * 2 * Bq * Hh; i += stride) {
        d_h[0][i] = 0.f;
        d_h[1][i] = 0.f;
        d_h[2][i] = 0.f;   // t=0 reads hprev from ring slot 2 -> must be zero
        d_c[i]    = 0.f;
    }
}

// ---------------- one LSTM cell (t, l, dir): 64 batch x 16 hidden units per block ----------------
// C tile [64, 64]: 64 batch rows x (4 gates x 16 units). 4 warps, 2x2 grid of 32x32 tiles.
// smem: 3 stages x (A 64x16 + B 64x16) = 24 KB -> 7 blocks/SM; full wave (1024 blocks)
// is single-residency (7 x 148 = 1036). One __syncthreads per K-iter:
// at iter it, load stage (it+2)%3, whose last reader was iter it-1 (protected by this barrier).
template <int KIN>
__device__ __forceinline__ void lstm_cell(int t, int l, int dir, float* smem) {
    constexpr int NIT = (KIN + Hh) / 16;
    const int tid = threadIdx.x;
    const int mt  = blockIdx.x;   // 0..3
    const int jt  = blockIdx.y;   // 0..31
    const int b0  = mt * 64, j0 = jt * 16;

    const int rb = (t + 2) % 3, wb = t % 3;
    const float* __restrict__ hprevD = d_h[rb] + (l * 2 + dir) * Bq * Hh;
    float* __restrict__       houtD  = d_h[wb] + (l * 2 + dir) * Bq * Hh;
    float* __restrict__       cstD   = d_c     + (l * 2 + dir) * Bq * Hh;
    const float* __restrict__ xbase  = (KIN == Ee) ? (d_x0 + t * Bq * Ee)
                                                   : (d_h[wb] + (l - 1) * 2 * Bq * Hh);
    const float* __restrict__ WihD   = (KIN == Ee) ? (d_Wih0 + dir * G4 * Ee)
                                                   : (d_WihL + ((l - 1) * 2 + dir) * G4 * 1024);
    const float* __restrict__ WhhD   = (KIN == Ee) ? (d_Whh0 + dir * G4 * Hh)
                                                   : (d_WhhL + ((l - 1) * 2 + dir) * G4 * Hh);

    // ---- hoisted cp.async geometry: 128 threads cover A(64rows x 4grps)/2 + B/2 per q ----
    const int lrow = tid >> 2, lgrp = tid & 3;
    uint32_t aSm[2], bSm[2];
    int aRow[2], bIh[2], bHh[2];
    #pragma unroll
    for (int q = 0; q < 2; ++q) {
        int row = lrow + q * 32;
        uint32_t sw = ((lgrp ^ (row & 3)) << 2);
        aSm[q]  = row * 16 + sw;
        bSm[q]  = row * 16 + sw;
        aRow[q] = b0 + row;
        int wrow = (row >> 4) * Hh + j0 + (row & 15);
        bIh[q]  = wrow * KIN + lgrp * 4;
        bHh[q]  = wrow * Hh + lgrp * 4;
    }

    auto load_stage = [&](int it, int buf) {
        const int k0 = it * 16;
        const int kk = k0 + lgrp * 4;
        float* sA = smem + buf * 2048;
        float* sB = sA + 1024;
        if (kk < KIN) {
            const float* ab = (KIN == Ee) ? xbase : (xbase + (kk >> 9) * Bq * Hh);
            const int ks = (KIN == Ee) ? kk : (kk & 511);
            const int as = (KIN == Ee) ? Ee : Hh;
            #pragma unroll
            for (int q = 0; q < 2; ++q) cp16(&sA[aSm[q]], ab + aRow[q] * as + ks);
            #pragma unroll
            for (int q = 0; q < 2; ++q) cp16(&sB[bSm[q]], WihD + bIh[q] + k0);
        } else {
            const int ko = kk - KIN;
            #pragma unroll
            for (int q = 0; q < 2; ++q) cp16(&sA[aSm[q]], hprevD + aRow[q] * Hh + ko);
            #pragma unroll
            for (int q = 0; q < 2; ++q) cp16(&sB[bSm[q]], WhhD + bHh[q] + (k0 - KIN));
        }
        cp_commit();
    };

    const int lane = tid & 31, wid = tid >> 5;
    const int wm = wid & 1, wn = wid >> 1;     // 2x2 warp grid, 32x32 warp tile
    const int g = lane >> 2, tg = lane & 3;

    // hoisted fragment smem offsets (floats, stage-relative)
    const uint32_t asw = ((tg ^ (g & 3)) << 2);
    uint32_t aOff[2][2], bOff[4];
    #pragma unroll
    for (int mi = 0; mi < 2; ++mi) {
        int r = wm * 32 + mi * 16 + g;
        aOff[mi][0] = r * 16 + asw;
        aOff[mi][1] = (r + 8) * 16 + asw;
    }
    #pragma unroll
    for (int ni = 0; ni < 4; ++ni) {
        int n = wn * 32 + ni * 8 + g;
        bOff[ni] = 1024 + n * 16 + ((tg ^ (n & 3)) << 2);
    }

    float acc[2][4][4];
    #pragma unroll
    for (int i = 0; i < 2; i++)
        #pragma unroll
        for (int j = 0; j < 4; j++)
            #pragma unroll
            for (int k = 0; k < 4; k++) acc[i][j][k] = 0.f;

    load_stage(0, 0);
    if (NIT > 1) load_stage(1, 1);
    int rdOff = 0, ldBuf = 2;   // rotating stage offsets (no div/mod)
    for (int it = 0; it < NIT; ++it) {
        if (it + 1 < NIT) cp_wait<1>();   // stage it landed (it+1 may fly)
        else              cp_wait<0>();
        __syncthreads();                  // also: all warps done reading stage (it+2)%3 (iter it-1)
        if (it + 2 < NIT) {
            load_stage(it + 2, ldBuf);
            if (++ldBuf == 3) ldBuf = 0;
        }
        const float* A = smem + rdOff;
        if ((rdOff += 2048) == 6144) rdOff = 0;

        float4 bv[4];
        #pragma unroll
        for (int ni = 0; ni < 4; ++ni)
            bv[ni] = *reinterpret_cast<const float4*>(A + bOff[ni]);
        #pragma unroll
        for (int mi = 0; mi < 2; ++mi) {
            float4 a0 = *reinterpret_cast<const float4*>(A + aOff[mi][0]);
            float4 a1 = *reinterpret_cast<const float4*>(A + aOff[mi][1]);
            #pragma unroll
            for (int ni = 0; ni < 4; ++ni) {
                mma_tf32(acc[mi][ni],
                         __float_as_uint(a0.x), __float_as_uint(a1.x),
                         __float_as_uint(a0.y), __float_as_uint(a1.y),
                         __float_as_uint(bv[ni].x), __float_as_uint(bv[ni].y));
                mma_tf32(acc[mi][ni],
                         __float_as_uint(a0.z), __float_as_uint(a1.z),
                         __float_as_uint(a0.w), __float_as_uint(a1.w),
                         __float_as_uint(bv[ni].z), __float_as_uint(bv[ni].w));
            }
        }
    }
    __syncthreads();   // all reads of stage buffers done before reuse as gt

    // ---- epilogue: restage gates to smem gt[64][80] ----
    float* gt = smem;
    #pragma unroll
    for (int mi = 0; mi < 2; ++mi)
        #pragma unroll
        for (int ni = 0; ni < 4; ++ni) {
            int r  = wm * 32 + mi * 16 + g;
            int cc = wn * 32 + ni * 8 + 2 * tg;
            gt[r * 80 + cc]           = acc[mi][ni][0];
            gt[r * 80 + cc + 1]       = acc[mi][ni][1];
            gt[(r + 8) * 80 + cc]     = acc[mi][ni][2];
            gt[(r + 8) * 80 + cc + 1] = acc[mi][ni][3];
        }
    __syncthreads();

    // elementwise LSTM cell update: 64 rows x 16 units, 8 cells/thread (fast activations)
    const int jj = tid & 15;           // unit within tile
    const int rbase = tid >> 4;        // 0..7
    const float* biasD = d_bias + (l * 2 + dir) * G4;
    const int j = j0 + jj;
    const float bi = biasD[0 * Hh + j];
    const float bf = biasD[1 * Hh + j];
    const float bg = biasD[2 * Hh + j];
    const float bo = biasD[3 * Hh + j];
    const int jp = j0 + (((jj & 3) << 2) | (jj >> 2));   // perm16'd h storage position
    #pragma unroll
    for (int q = 0; q < 8; ++q) {
        int row = rbase + q * 8;       // 0..63
        int b = b0 + row;
        float gi = gt[row * 80 +  0 + jj] + bi;
        float gf = gt[row * 80 + 16 + jj] + bf;
        float gg = gt[row * 80 + 32 + jj] + bg;
        float go = gt[row * 80 + 48 + jj] + bo;
        float i_ = sigf(gi), f_ = sigf(gf), g_ = tanhf_fast(gg), o_ = sigf(go);
        float cn = fmaf(f_, cstD[b * Hh + j], i_ * g_);
        cstD[b * Hh + j]   = cn;
        houtD[b * Hh + jp] = tf32r(o_ * tanhf_fast(cn));   // permuted store; tf32 pre-round (rna)
    }
}

// ---------------- wavefront kernel ----------------
// grid = (4 mtiles, 32 jtiles, ncells*2); blockIdx.z = (cell_idx << 1) | dir
__global__ __launch_bounds__(128, 7) void lstm_wave(int w, int lmin) {
    __shared__ __align__(16) float smem[6144];   // 3 stages x 2048 floats = 24 KB
    const int cell = blockIdx.z >> 1;
    const int dir  = blockIdx.z & 1;
    const int l    = lmin + cell;
    const int t    = w - l;
    if (t < 0 || t >= Tn) return;
    if (l == 0) lstm_cell<Ee>(t, 0, dir, smem);
    else        lstm_cell<1024>(t, l, dir, smem);
}

// ---------------- final FC + softmax ----------------
__global__ __launch_bounds__(256) void fc_softmax(const float* __restrict__ fcw,
                                                  const float* __restrict__ fcb,
                                                  float* __restrict__ out) {
    const int b = blockIdx.x;
    const int tid = threadIdx.x, lane = tid & 31, w = tid >> 5;
    __shared__ float sv[64];
    const float* __restrict__ hf = d_h[(Tn - 1) % 3];   // t=127 wrote ring slot 1
    float acc[8] = {0, 0, 0, 0, 0, 0, 0, 0};
    for (int k = lane; k < 8192; k += 32) {
        int s = k >> 10, r = k & 1023, j = r & 511;
        float hv = (r & 512) ? d_c[(s * Bq + b) * Hh + j]
                             : hf[(s * Bq + b) * Hh + perm16(j)];   // h stored permuted
        #pragma unroll
        for (int q = 0; q < 8; ++q)
            acc[q] = fmaf(hv, fcw[(w * 8 + q) * 8192 + k], acc[q]);
    }
    #pragma unroll
    for (int q = 0; q < 8; ++q) {
        float v = acc[q];
        #pragma unroll
        for (int off = 16; off; off >>= 1) v += __shfl_xor_sync(0xffffffffu, v, off);
        if (lane == 0) sv[w * 8 + q] = v + fcb[w * 8 + q];
    }
    __syncthreads();
    if (tid < 32) {
        float v0 = sv[tid], v1 = sv[tid + 32];
        float m = fmaxf(v0, v1);
        #pragma unroll
        for (int off = 16; off; off >>= 1) m = fmaxf(m, __shfl_xor_sync(0xffffffffu, m, off));
        float e0 = expf(v0 - m), e1 = expf(v1 - m);
        float s = e0 + e1;
        #pragma unroll
        for (int off = 16; off; off >>= 1) s += __shfl_xor_sync(0xffffffffu, s, off);
        float inv = 1.0f / s;
        out[b * 64 + tid]      = e0 * inv;
        out[b * 64 + 32 + tid] = e1 * inv;
    }
}

// ---------------- launch ----------------
extern "C" void kernel_launch(void* const* d_in, const int* in_sizes, int n_in,
                              void* d_out, int out_size) {
    const int*   tokens = (const int*)  d_in[0];
    const float* embed  = (const float*)d_in[1];
    const float* Wih0   = (const float*)d_in[2];
    const float* Whh0   = (const float*)d_in[3];
    const float* bih0   = (const float*)d_in[4];
    const float* bhh0   = (const float*)d_in[5];
    const float* Wih    = (const float*)d_in[6];
    const float* Whh    = (const float*)d_in[7];
    const float* bih    = (const float*)d_in[8];
    const float* bhh    = (const float*)d_in[9];
    const float* fcw    = (const float*)d_in[10];
    const float* fcb    = (const float*)d_in[11];
    float*       out    = (float*)d_out;

    init_kernel<<<512, 256>>>(tokens, embed, Wih0, Whh0, bih0, bhh0, Wih, Whh, bih, bhh);

    // wavefront schedule: cells (t, l) with t + l == w are independent
    for (int w = 0; w <= (Tn - 1) + (Ln - 1); ++w) {
        int lmin = max(0, w - (Tn - 1));
        int lmax = min(Ln - 1, w);
        int ncells = lmax - lmin + 1;
        dim3 grid(4, 32, ncells * 2);
        lstm_wave<<<grid, 128>>>(w, lmin);
    }
    fc_softmax<<<Bq, 256>>>(fcw, fcb, out);
}